// round 1
// baseline (speedup 1.0000x reference)
#include <cuda_runtime.h>
#include <cuda_bf16.h>

#define Bb 32
#define Ss 2048
#define Dd 1024
#define NSPLIT 8
#define SCHUNK (Ss / NSPLIT)   // 256

// ---------------- scratch (device globals; no allocation allowed) ----------------
__device__ alignas(16) __nv_bfloat16 g_Xbf[(size_t)Bb * Ss * Dd];   // 128 MB masked bf16 copy of X
__device__ alignas(16) __nv_bfloat16 g_Wt[(size_t)Dd * Dd];         // W_local transposed, bf16: Wt[e][d] = Wl[d][e]
__device__ float g_gsum_part[NSPLIT * Bb * Dd];
__device__ float g_gp[Bb * Dd];
__device__ float g_v[Bb * Dd];       // v[b] = W_local @ gp[b]
__device__ float g_nrm[Bb * Ss];     // ||x @ W_local||^2 per token
__device__ float g_att[Bb * Ss];
__device__ float g_out_part[NSPLIT * Bb * Dd];

// ---------------- K0: W_local -> bf16 transposed (N-major for mma B frags) -------
__global__ void k_transpose(const float* __restrict__ Wl) {
    __shared__ float tile[32][33];
    int x = blockIdx.x * 32 + threadIdx.x;
    int y = blockIdx.y * 32 + threadIdx.y;
    tile[threadIdx.y][threadIdx.x] = Wl[(size_t)y * Dd + x];
    __syncthreads();
    int xo = blockIdx.y * 32 + threadIdx.x;   // d
    int yo = blockIdx.x * 32 + threadIdx.y;   // e
    g_Wt[(size_t)yo * Dd + xo] = __float2bfloat16(tile[threadIdx.x][threadIdx.y]);
}

// ---------------- K1: mask + seq-sum partials + bf16 convert ----------------------
__global__ void k_prep(const float* __restrict__ X, const int* __restrict__ lengths) {
    int b = blockIdx.y;
    int z = blockIdx.z;
    int d = blockIdx.x * 256 + threadIdx.x;
    int len = lengths[b];
    int s0 = z * SCHUNK;
    const float* Xb = X + ((size_t)b * Ss) * Dd + d;
    __nv_bfloat16* Xo = g_Xbf + ((size_t)b * Ss) * Dd + d;
    int zlim = (len + 127) & ~127; if (zlim > Ss) zlim = Ss;  // zero up to 128-row boundary

    float a0 = 0.f, a1 = 0.f, a2 = 0.f, a3 = 0.f;
    int send = min(len, s0 + SCHUNK);
    int s = s0;
    for (; s + 4 <= send; s += 4) {
        float x0 = Xb[(size_t)(s    ) * Dd];
        float x1 = Xb[(size_t)(s + 1) * Dd];
        float x2 = Xb[(size_t)(s + 2) * Dd];
        float x3 = Xb[(size_t)(s + 3) * Dd];
        a0 += x0; a1 += x1; a2 += x2; a3 += x3;
        Xo[(size_t)(s    ) * Dd] = __float2bfloat16(x0);
        Xo[(size_t)(s + 1) * Dd] = __float2bfloat16(x1);
        Xo[(size_t)(s + 2) * Dd] = __float2bfloat16(x2);
        Xo[(size_t)(s + 3) * Dd] = __float2bfloat16(x3);
    }
    for (; s < send; ++s) {
        float x = Xb[(size_t)s * Dd];
        a0 += x;
        Xo[(size_t)s * Dd] = __float2bfloat16(x);
    }
    int zs = max(len, s0), ze = min(zlim, s0 + SCHUNK);
    for (int sz = zs; sz < ze; ++sz) Xo[(size_t)sz * Dd] = __float2bfloat16(0.f);

    g_gsum_part[((size_t)z * Bb + b) * Dd + d] = (a0 + a1) + (a2 + a3);
}

// ---------------- K2: gp = l2norm(gsum @ Wg); v = Wl @ gp -------------------------
__global__ void k_gpv(const float* __restrict__ Wg, const float* __restrict__ Wl) {
    __shared__ float sh[Dd];
    __shared__ float red[32];
    int b = blockIdx.x, t = threadIdx.x;
    int lane = t & 31, warp = t >> 5;

    float gs = 0.f;
    for (int z = 0; z < NSPLIT; ++z) gs += g_gsum_part[((size_t)z * Bb + b) * Dd + t];
    sh[t] = gs;
    __syncthreads();

    float acc = 0.f;
    #pragma unroll 8
    for (int d2 = 0; d2 < Dd; ++d2) acc += sh[d2] * Wg[(size_t)d2 * Dd + t];

    float sq = acc * acc;
    #pragma unroll
    for (int o = 16; o; o >>= 1) sq += __shfl_xor_sync(0xffffffffu, sq, o);
    if (lane == 0) red[warp] = sq;
    __syncthreads();
    if (warp == 0) {
        float v2 = red[lane];
        #pragma unroll
        for (int o = 16; o; o >>= 1) v2 += __shfl_xor_sync(0xffffffffu, v2, o);
        if (lane == 0) red[0] = v2;
    }
    __syncthreads();
    float gpv = acc * rsqrtf(fmaxf(red[0], 1e-12f));
    g_gp[b * Dd + t] = gpv;
    __syncthreads();          // all reads of sh (gsum) are done; safe to reuse
    sh[t] = gpv;
    __syncthreads();

    // v[dd] = Wl[dd,:] . gp   (one warp per dd, coalesced over e)
    for (int dd = warp; dd < Dd; dd += 32) {
        const float* wr = Wl + (size_t)dd * Dd;
        float a = 0.f;
        #pragma unroll 4
        for (int e = lane; e < Dd; e += 32) a += wr[e] * sh[e];
        #pragma unroll
        for (int o = 16; o; o >>= 1) a += __shfl_xor_sync(0xffffffffu, a, o);
        if (lane == 0) g_v[b * Dd + dd] = a;
    }
}

// ---------------- K3: n[row] = || Xbf[row,:] @ Wl ||^2 via bf16 mma.sync ----------
__device__ __forceinline__ void mma_bf16(float c[4], unsigned a0, unsigned a1, unsigned a2,
                                         unsigned a3, unsigned b0, unsigned b1) {
    asm volatile(
        "mma.sync.aligned.m16n8k16.row.col.f32.bf16.bf16.f32 "
        "{%0,%1,%2,%3},{%4,%5,%6,%7},{%8,%9},{%0,%1,%2,%3};\n"
        : "+f"(c[0]), "+f"(c[1]), "+f"(c[2]), "+f"(c[3])
        : "r"(a0), "r"(a1), "r"(a2), "r"(a3), "r"(b0), "r"(b1));
}

// 128x128x32 block tile, 8 warps (2 M x 4 N), warp tile 64x32. smem pitch 20 u32/row.
__global__ __launch_bounds__(256) void k_norm(const int* __restrict__ lengths) {
    const int rows_base = blockIdx.x * 128;
    {
        int b  = rows_base >> 11;
        int s0 = rows_base & (Ss - 1);
        if (s0 >= lengths[b]) return;   // entire tile masked
    }
    __shared__ alignas(16) unsigned As[128 * 20];
    __shared__ alignas(16) unsigned Bs[128 * 20];
    __shared__ float ns4[4][128];

    const int tid = threadIdx.x;
    const int warp = tid >> 5, lane = tid & 31;
    const int wm = warp & 1, wn = warp >> 1;
    const int gid = lane >> 2, tig = lane & 3;
    const int r0 = tid >> 2, seg = tid & 3;

    const uint4* Ag = reinterpret_cast<const uint4*>(g_Xbf) + (size_t)rows_base * (Dd / 8);

    float rs[4][2];
    #pragma unroll
    for (int i = 0; i < 4; ++i) { rs[i][0] = 0.f; rs[i][1] = 0.f; }

    for (int nt = 0; nt < 8; ++nt) {
        const uint4* Bg = reinterpret_cast<const uint4*>(g_Wt) + (size_t)(nt * 128) * (Dd / 8);

        float acc[4][4][4];
        #pragma unroll
        for (int i = 0; i < 4; ++i)
            #pragma unroll
            for (int j = 0; j < 4; ++j)
                #pragma unroll
                for (int q = 0; q < 4; ++q) acc[i][j][q] = 0.f;

        uint4 ra0 = Ag[(size_t)r0 * 128 + seg];
        uint4 ra1 = Ag[(size_t)(r0 + 64) * 128 + seg];
        uint4 rb0 = Bg[(size_t)r0 * 128 + seg];
        uint4 rb1 = Bg[(size_t)(r0 + 64) * 128 + seg];

        for (int kt = 0; kt < 32; ++kt) {
            *reinterpret_cast<uint4*>(&As[r0 * 20 + seg * 4])        = ra0;
            *reinterpret_cast<uint4*>(&As[(r0 + 64) * 20 + seg * 4]) = ra1;
            *reinterpret_cast<uint4*>(&Bs[r0 * 20 + seg * 4])        = rb0;
            *reinterpret_cast<uint4*>(&Bs[(r0 + 64) * 20 + seg * 4]) = rb1;
            __syncthreads();
            if (kt < 31) {   // prefetch next k-slab while computing this one
                ra0 = Ag[(size_t)r0 * 128 + (kt + 1) * 4 + seg];
                ra1 = Ag[(size_t)(r0 + 64) * 128 + (kt + 1) * 4 + seg];
                rb0 = Bg[(size_t)r0 * 128 + (kt + 1) * 4 + seg];
                rb1 = Bg[(size_t)(r0 + 64) * 128 + (kt + 1) * 4 + seg];
            }
            #pragma unroll
            for (int k2 = 0; k2 < 2; ++k2) {
                unsigned af[4][4];
                #pragma unroll
                for (int i = 0; i < 4; ++i) {
                    int r = wm * 64 + i * 16 + gid;
                    int base = r * 20 + k2 * 8 + tig;
                    af[i][0] = As[base];
                    af[i][1] = As[base + 160];   // +8 rows
                    af[i][2] = As[base + 4];     // +8 cols
                    af[i][3] = As[base + 164];
                }
                unsigned bq[4][2];
                #pragma unroll
                for (int j = 0; j < 4; ++j) {
                    int n = wn * 32 + j * 8 + gid;
                    int base = n * 20 + k2 * 8 + tig;
                    bq[j][0] = Bs[base];
                    bq[j][1] = Bs[base + 4];
                }
                #pragma unroll
                for (int i = 0; i < 4; ++i)
                    #pragma unroll
                    for (int j = 0; j < 4; ++j)
                        mma_bf16(acc[i][j], af[i][0], af[i][1], af[i][2], af[i][3],
                                 bq[j][0], bq[j][1]);
            }
            __syncthreads();
        }
        // reduce this N-tile's squares into per-thread row sums (deterministic)
        #pragma unroll
        for (int i = 0; i < 4; ++i)
            #pragma unroll
            for (int j = 0; j < 4; ++j) {
                rs[i][0] += acc[i][j][0] * acc[i][j][0] + acc[i][j][1] * acc[i][j][1];
                rs[i][1] += acc[i][j][2] * acc[i][j][2] + acc[i][j][3] * acc[i][j][3];
            }
    }
    #pragma unroll
    for (int i = 0; i < 4; ++i) {
        float p0 = rs[i][0], p1 = rs[i][1];
        p0 += __shfl_xor_sync(0xffffffffu, p0, 1);
        p0 += __shfl_xor_sync(0xffffffffu, p0, 2);
        p1 += __shfl_xor_sync(0xffffffffu, p1, 1);
        p1 += __shfl_xor_sync(0xffffffffu, p1, 2);
        if (tig == 0) {
            int r = wm * 64 + i * 16 + gid;
            ns4[wn][r]     = p0;
            ns4[wn][r + 8] = p1;
        }
    }
    __syncthreads();
    for (int r = tid; r < 128; r += 256)
        g_nrm[rows_base + r] = (ns4[0][r] + ns4[1][r]) + (ns4[2][r] + ns4[3][r]);
}

// ---------------- K4: attention = (x . v[b]) * rsqrt(max(n, eps)) -----------------
__global__ void k_att(const float* __restrict__ X, const int* __restrict__ lengths) {
    int token = blockIdx.x * 8 + (threadIdx.x >> 5);
    int lane = threadIdx.x & 31;
    int b = token >> 11;
    int s = token & (Ss - 1);
    if (s >= lengths[b]) return;   // warp-uniform exit; masked att never read downstream

    const float4* x4 = reinterpret_cast<const float4*>(X + (size_t)token * Dd);
    const float4* v4 = reinterpret_cast<const float4*>(g_v + (size_t)b * Dd);
    float t = 0.f;
    #pragma unroll
    for (int i = 0; i < 8; ++i) {
        float4 xv = x4[lane + i * 32];
        float4 vv = v4[lane + i * 32];
        t += xv.x * vv.x + xv.y * vv.y + xv.z * vv.z + xv.w * vv.w;
    }
    #pragma unroll
    for (int o = 16; o; o >>= 1) t += __shfl_xor_sync(0xffffffffu, t, o);
    if (lane == 0) g_att[token] = t * rsqrtf(fmaxf(g_nrm[token], 1e-12f));
}

// ---------------- K5: out partials = sum_s att * X --------------------------------
__global__ void k_out(const float* __restrict__ X, const int* __restrict__ lengths) {
    int b = blockIdx.y, z = blockIdx.z;
    int d = blockIdx.x * 256 + threadIdx.x;
    int len = lengths[b];
    int s0 = z * SCHUNK, send = min(len, s0 + SCHUNK);
    const float* Xb = X + ((size_t)b * Ss) * Dd + d;
    const float* ab = g_att + b * Ss;
    float a0 = 0.f, a1 = 0.f, a2 = 0.f, a3 = 0.f;
    int s = s0;
    for (; s + 4 <= send; s += 4) {
        a0 += ab[s    ] * Xb[(size_t)(s    ) * Dd];
        a1 += ab[s + 1] * Xb[(size_t)(s + 1) * Dd];
        a2 += ab[s + 2] * Xb[(size_t)(s + 2) * Dd];
        a3 += ab[s + 3] * Xb[(size_t)(s + 3) * Dd];
    }
    for (; s < send; ++s) a0 += ab[s] * Xb[(size_t)s * Dd];
    g_out_part[((size_t)z * Bb + b) * Dd + d] = (a0 + a1) + (a2 + a3);
}

// ---------------- K6: combine partials --------------------------------------------
__global__ void k_final(float* __restrict__ out) {
    int i = blockIdx.x * 256 + threadIdx.x;
    float a = 0.f;
    #pragma unroll
    for (int z = 0; z < NSPLIT; ++z) a += g_out_part[(size_t)z * Bb * Dd + i];
    out[i] = a;
}

// ---------------- launch -----------------------------------------------------------
extern "C" void kernel_launch(void* const* d_in, const int* in_sizes, int n_in,
                              void* d_out, int out_size) {
    const float* X       = (const float*)d_in[0];
    const int*   lengths = (const int*)d_in[1];
    const float* Wg      = (const float*)d_in[2];
    const float* Wl      = (const float*)d_in[3];
    float* out = (float*)d_out;

    k_transpose<<<dim3(Dd / 32, Dd / 32), dim3(32, 32)>>>(Wl);
    k_prep<<<dim3(Dd / 256, Bb, NSPLIT), 256>>>(X, lengths);
    k_gpv<<<Bb, 1024>>>(Wg, Wl);
    k_norm<<<(Bb * Ss) / 128, 256>>>(lengths);
    k_att<<<(Bb * Ss) / 8, 256>>>(X, lengths);
    k_out<<<dim3(Dd / 256, Bb, NSPLIT), 256>>>(X, lengths);
    k_final<<<(Bb * Dd) / 256, 256>>>(out);
}

// round 4
// speedup vs baseline: 1.2067x; 1.2067x over previous
#include <cuda_runtime.h>
#include <cuda_bf16.h>
#include <cstdint>

#define Bb 32
#define Ss 2048
#define Dd 1024
#define NSPLIT 8
#define SCHUNK (Ss / NSPLIT)

// ---------------- scratch (device globals; no allocation allowed) ----------------
__device__ alignas(16) __nv_bfloat16 g_Xbf[(size_t)Bb * Ss * Dd];   // masked bf16 X
__device__ alignas(16) __nv_bfloat16 g_Wt[(size_t)Dd * Dd];         // Wt[e][d] = Wl[d][e]
__device__ alignas(16) float g_Wlt[(size_t)Dd * Dd];                // fp32 transpose of Wl
__device__ float g_gsum_part[NSPLIT * Bb * Dd];
__device__ float g_gppart[8 * Bb * Dd];
__device__ float g_gp[Bb * Dd];       // RAW (unnormalized) gp
__device__ float g_rsq[Bb];
__device__ float g_vpart[16 * Bb * Dd];
__device__ float g_v[Bb * Dd];        // v = (Wl @ gp) * rsq   (fp32 exact)
__device__ float g_nrm[Bb * Ss];      // ||x @ Wl||^2 per token
__device__ float g_att[Bb * Ss];
__device__ float g_out_part[NSPLIT * Bb * Dd];

// ---------------- helpers ----------------------------------------------------------
__device__ __forceinline__ uint32_t smem_u32(const void* p) {
    return (uint32_t)__cvta_generic_to_shared(p);
}
__device__ __forceinline__ void cpa16(uint32_t dst, const void* src) {
    asm volatile("cp.async.cg.shared.global [%0], [%1], 16;\n" :: "r"(dst), "l"(src));
}
__device__ __forceinline__ void ldsm4(uint32_t& r0, uint32_t& r1, uint32_t& r2, uint32_t& r3,
                                      uint32_t addr) {
    asm volatile("ldmatrix.sync.aligned.m8n8.x4.shared.b16 {%0,%1,%2,%3}, [%4];"
                 : "=r"(r0), "=r"(r1), "=r"(r2), "=r"(r3) : "r"(addr));
}
__device__ __forceinline__ void mma_bf16(float c[4], uint32_t a0, uint32_t a1, uint32_t a2,
                                         uint32_t a3, uint32_t b0, uint32_t b1) {
    asm volatile(
        "mma.sync.aligned.m16n8k16.row.col.f32.bf16.bf16.f32 "
        "{%0,%1,%2,%3},{%4,%5,%6,%7},{%8,%9},{%0,%1,%2,%3};\n"
        : "+f"(c[0]), "+f"(c[1]), "+f"(c[2]), "+f"(c[3])
        : "r"(a0), "r"(a1), "r"(a2), "r"(a3), "r"(b0), "r"(b1));
}

// ---------------- K0: transpose Wl -> bf16 g_Wt + fp32 g_Wlt ----------------------
__global__ void k_transpose(const float* __restrict__ Wl) {
    __shared__ float tile[32][33];
    int x = blockIdx.x * 32 + threadIdx.x;
    int y = blockIdx.y * 32 + threadIdx.y;
    tile[threadIdx.y][threadIdx.x] = Wl[(size_t)y * Dd + x];
    __syncthreads();
    int xo = blockIdx.y * 32 + threadIdx.x;   // d
    int yo = blockIdx.x * 32 + threadIdx.y;   // e
    float v = tile[threadIdx.x][threadIdx.y];
    g_Wt[(size_t)yo * Dd + xo]  = __float2bfloat16(v);
    g_Wlt[(size_t)yo * Dd + xo] = v;
}

// ---------------- K1: mask + seq-sum partials + bf16 convert -----------------------
__global__ void k_prep(const float* __restrict__ X, const int* __restrict__ lengths) {
    int b = blockIdx.y;
    int z = blockIdx.z;
    int d = blockIdx.x * 256 + threadIdx.x;
    int len = lengths[b];
    int s0 = z * SCHUNK;
    const float* Xb = X + ((size_t)b * Ss) * Dd + d;
    __nv_bfloat16* Xo = g_Xbf + ((size_t)b * Ss) * Dd + d;
    int zlim = (len + 127) & ~127; if (zlim > Ss) zlim = Ss;

    float a0 = 0.f, a1 = 0.f, a2 = 0.f, a3 = 0.f;
    int send = min(len, s0 + SCHUNK);
    int s = s0;
    for (; s + 4 <= send; s += 4) {
        float x0 = Xb[(size_t)(s    ) * Dd];
        float x1 = Xb[(size_t)(s + 1) * Dd];
        float x2 = Xb[(size_t)(s + 2) * Dd];
        float x3 = Xb[(size_t)(s + 3) * Dd];
        a0 += x0; a1 += x1; a2 += x2; a3 += x3;
        Xo[(size_t)(s    ) * Dd] = __float2bfloat16(x0);
        Xo[(size_t)(s + 1) * Dd] = __float2bfloat16(x1);
        Xo[(size_t)(s + 2) * Dd] = __float2bfloat16(x2);
        Xo[(size_t)(s + 3) * Dd] = __float2bfloat16(x3);
    }
    for (; s < send; ++s) {
        float x = Xb[(size_t)s * Dd];
        a0 += x;
        Xo[(size_t)s * Dd] = __float2bfloat16(x);
    }
    int zs = max(len, s0), ze = min(zlim, s0 + SCHUNK);
    for (int sz = zs; sz < ze; ++sz) Xo[(size_t)sz * Dd] = __float2bfloat16(0.f);

    g_gsum_part[((size_t)z * Bb + b) * Dd + d] = (a0 + a1) + (a2 + a3);
}

// ---------------- gp chain: read Wg once, b-batched --------------------------------
__global__ void k_gp1(const float* __restrict__ Wg) {
    __shared__ float sgs[32][128];
    int tid = threadIdx.x;
    int y = blockIdx.y;                 // d2-split of 8
    for (int idx = tid; idx < 32 * 128; idx += 256) {
        int b2 = idx >> 7, d = idx & 127;
        float s = 0.f;
        #pragma unroll
        for (int z = 0; z < NSPLIT; ++z)
            s += g_gsum_part[((size_t)z * Bb + b2) * Dd + y * 128 + d];
        sgs[b2][d] = s;
    }
    __syncthreads();
    int col = blockIdx.x * 256 + tid;
    float acc[32];
    #pragma unroll
    for (int b2 = 0; b2 < 32; ++b2) acc[b2] = 0.f;
    for (int d2 = 0; d2 < 128; ++d2) {
        float w = Wg[(size_t)(y * 128 + d2) * Dd + col];
        #pragma unroll
        for (int b2 = 0; b2 < 32; ++b2) acc[b2] = fmaf(sgs[b2][d2], w, acc[b2]);
    }
    #pragma unroll
    for (int b2 = 0; b2 < 32; ++b2)
        g_gppart[((size_t)y * Bb + b2) * Dd + col] = acc[b2];
}

__global__ void k_gp2() {
    int b = blockIdx.x, tid = threadIdx.x;
    int lane = tid & 31, warp = tid >> 5;
    __shared__ float red[8];
    float sq = 0.f;
    for (int c = tid; c < Dd; c += 256) {
        float s = 0.f;
        #pragma unroll
        for (int z = 0; z < 8; ++z) s += g_gppart[((size_t)z * Bb + b) * Dd + c];
        g_gp[b * Dd + c] = s;
        sq += s * s;
    }
    #pragma unroll
    for (int o = 16; o; o >>= 1) sq += __shfl_xor_sync(0xffffffffu, sq, o);
    if (lane == 0) red[warp] = sq;
    __syncthreads();
    if (tid == 0) {
        float t = 0.f;
        #pragma unroll
        for (int w = 0; w < 8; ++w) t += red[w];
        g_rsq[b] = rsqrtf(fmaxf(t, 1e-12f));
    }
}

// ---------------- v chain: v = (Wl @ gp) * rsq, read Wlt once ----------------------
__global__ void k_v1() {
    __shared__ float sgp[32][64];
    int tid = threadIdx.x;
    int y = blockIdx.y;                 // e-split of 16
    for (int idx = tid; idx < 32 * 64; idx += 256) {
        int b2 = idx >> 6, e = idx & 63;
        sgp[b2][e] = g_gp[b2 * Dd + y * 64 + e];
    }
    __syncthreads();
    int col = blockIdx.x * 256 + tid;
    float acc[32];
    #pragma unroll
    for (int b2 = 0; b2 < 32; ++b2) acc[b2] = 0.f;
    for (int e = 0; e < 64; ++e) {
        float w = g_Wlt[(size_t)(y * 64 + e) * Dd + col];
        #pragma unroll
        for (int b2 = 0; b2 < 32; ++b2) acc[b2] = fmaf(sgp[b2][e], w, acc[b2]);
    }
    #pragma unroll
    for (int b2 = 0; b2 < 32; ++b2)
        g_vpart[((size_t)y * Bb + b2) * Dd + col] = acc[b2];
}

__global__ void k_v2() {
    int i = blockIdx.x * 256 + threadIdx.x;
    int b = i >> 10;
    float s = 0.f;
    #pragma unroll
    for (int z = 0; z < 16; ++z) s += g_vpart[(size_t)z * Bb * Dd + i];
    g_v[i] = s * g_rsq[b];
}

// ---------------- K3: HMMA GEMM, epilogue = row sums of squares only ---------------
#define PITCH 80
#define STG_BYTES (128 * PITCH)                   // 10240
#define SA_OFF(st) ((uint32_t)(st) * 2u * STG_BYTES)
#define SB_OFF(st) ((uint32_t)(st) * 2u * STG_BYTES + STG_BYTES)
#define REDN_OFF 81920
#define NORM_SMEM 84096

__device__ __forceinline__ void fill_stage(uint32_t sb, int st, const char* Abase,
                                           const char* Bbase, int ks, int tid) {
    #pragma unroll
    for (int rep = 0; rep < 2; ++rep) {
        int id = tid + rep * 256;
        int r = id >> 2, c = id & 3;
        uint32_t off = (uint32_t)(r * PITCH + c * 16);
        cpa16(sb + SA_OFF(st) + off, Abase + (size_t)r * 2048 + ks * 64 + c * 16);
        cpa16(sb + SB_OFF(st) + off, Bbase + (size_t)r * 2048 + ks * 64 + c * 16);
    }
}

__global__ void __launch_bounds__(256, 2) k_norm(const int* __restrict__ lengths) {
    extern __shared__ __align__(128) char sm[];
    const int rows_base = blockIdx.x * 128;
    const int b = rows_base >> 11;
    if ((rows_base & (Ss - 1)) >= lengths[b]) return;

    const uint32_t sb = smem_u32(sm);
    float* redN = (float*)(sm + REDN_OFF);   // [4][128]

    const int tid = threadIdx.x;
    const int warp = tid >> 5, lane = tid & 31;
    const int wm = warp & 1, wn = warp >> 1;
    const int gid = lane >> 2, tig = lane & 3;
    const uint32_t lanebyte = (uint32_t)((lane & 15) * PITCH + (lane >> 4) * 16);

    const char* Abase = (const char*)(g_Xbf + (size_t)rows_base * Dd);   // 2048 B/row

    float rsN[4][2];
    #pragma unroll
    for (int i = 0; i < 4; ++i) { rsN[i][0] = 0.f; rsN[i][1] = 0.f; }

    for (int nt = 0; nt < 8; ++nt) {
        const char* Bbase = (const char*)g_Wt + (size_t)nt * 128 * 2048;

        #pragma unroll
        for (int st = 0; st < 3; ++st) {
            fill_stage(sb, st, Abase, Bbase, st, tid);
            asm volatile("cp.async.commit_group;");
        }

        float acc[4][4][4];
        #pragma unroll
        for (int i = 0; i < 4; ++i)
            #pragma unroll
            for (int j = 0; j < 4; ++j)
                #pragma unroll
                for (int q = 0; q < 4; ++q) acc[i][j][q] = 0.f;

        for (int ks = 0; ks < 32; ++ks) {
            asm volatile("cp.async.wait_group 2;");
            __syncthreads();
            const uint32_t sa = sb + SA_OFF(ks & 3);
            const uint32_t sB = sb + SB_OFF(ks & 3);
            #pragma unroll
            for (int kg = 0; kg < 2; ++kg) {
                uint32_t a[4][4];
                #pragma unroll
                for (int i = 0; i < 4; ++i)
                    ldsm4(a[i][0], a[i][1], a[i][2], a[i][3],
                          sa + (uint32_t)((wm * 64 + i * 16) * PITCH + kg * 32) + lanebyte);
                uint32_t bb[2][4];
                #pragma unroll
                for (int j2 = 0; j2 < 2; ++j2)
                    ldsm4(bb[j2][0], bb[j2][1], bb[j2][2], bb[j2][3],
                          sB + (uint32_t)((wn * 32 + j2 * 16) * PITCH + kg * 32) + lanebyte);
                #pragma unroll
                for (int i = 0; i < 4; ++i)
                    #pragma unroll
                    for (int j = 0; j < 4; ++j)
                        mma_bf16(acc[i][j], a[i][0], a[i][1], a[i][2], a[i][3],
                                 bb[j >> 1][j & 1], bb[j >> 1][(j & 1) + 2]);
            }
            __syncthreads();
            if (ks + 3 < 32) fill_stage(sb, (ks + 3) & 3, Abase, Bbase, ks + 3, tid);
            asm volatile("cp.async.commit_group;");   // empty group when no fill
        }

        // epilogue: n += y^2 (no cancellation -> bf16-safe)
        #pragma unroll
        for (int j = 0; j < 4; ++j)
            #pragma unroll
            for (int i = 0; i < 4; ++i) {
                rsN[i][0] += acc[i][j][0] * acc[i][j][0] + acc[i][j][1] * acc[i][j][1];
                rsN[i][1] += acc[i][j][2] * acc[i][j][2] + acc[i][j][3] * acc[i][j][3];
            }
    }

    #pragma unroll
    for (int i = 0; i < 4; ++i) {
        #pragma unroll
        for (int h = 0; h < 2; ++h) {
            float n = rsN[i][h];
            n += __shfl_xor_sync(0xffffffffu, n, 1);
            n += __shfl_xor_sync(0xffffffffu, n, 2);
            if (tig == 0) redN[wn * 128 + wm * 64 + i * 16 + gid + h * 8] = n;
        }
    }
    __syncthreads();
    if (tid < 128) {
        float n = (redN[tid] + redN[128 + tid]) + (redN[256 + tid] + redN[384 + tid]);
        g_nrm[rows_base + tid] = n;
    }
}

// ---------------- K4: attention = (x . v[b]) * rsqrt(max(n, eps)) ------------------
__global__ void k_att(const float* __restrict__ X, const int* __restrict__ lengths) {
    int token = blockIdx.x * 8 + (threadIdx.x >> 5);
    int lane = threadIdx.x & 31;
    int b = token >> 11;
    int s = token & (Ss - 1);
    if (s >= lengths[b]) return;

    const float4* x4 = reinterpret_cast<const float4*>(X + (size_t)token * Dd);
    const float4* v4 = reinterpret_cast<const float4*>(g_v + (size_t)b * Dd);
    float t = 0.f;
    #pragma unroll
    for (int i = 0; i < 8; ++i) {
        float4 xv = x4[lane + i * 32];
        float4 vv = v4[lane + i * 32];
        t += xv.x * vv.x + xv.y * vv.y + xv.z * vv.z + xv.w * vv.w;
    }
    #pragma unroll
    for (int o = 16; o; o >>= 1) t += __shfl_xor_sync(0xffffffffu, t, o);
    if (lane == 0) g_att[token] = t * rsqrtf(fmaxf(g_nrm[token], 1e-12f));
}

// ---------------- K5: out partials = sum_s att * X ---------------------------------
__global__ void k_out(const float* __restrict__ X, const int* __restrict__ lengths) {
    int b = blockIdx.y, z = blockIdx.z;
    int d = blockIdx.x * 256 + threadIdx.x;
    int len = lengths[b];
    int s0 = z * SCHUNK, send = min(len, s0 + SCHUNK);
    const float* Xb = X + ((size_t)b * Ss) * Dd + d;
    const float* ab = g_att + b * Ss;
    float a0 = 0.f, a1 = 0.f, a2 = 0.f, a3 = 0.f;
    int s = s0;
    for (; s + 4 <= send; s += 4) {
        a0 += ab[s    ] * Xb[(size_t)(s    ) * Dd];
        a1 += ab[s + 1] * Xb[(size_t)(s + 1) * Dd];
        a2 += ab[s + 2] * Xb[(size_t)(s + 2) * Dd];
        a3 += ab[s + 3] * Xb[(size_t)(s + 3) * Dd];
    }
    for (; s < send; ++s) a0 += ab[s] * Xb[(size_t)s * Dd];
    g_out_part[((size_t)z * Bb + b) * Dd + d] = (a0 + a1) + (a2 + a3);
}

// ---------------- K6: combine partials ----------------------------------------------
__global__ void k_final(float* __restrict__ out) {
    int i = blockIdx.x * 256 + threadIdx.x;
    float a = 0.f;
    #pragma unroll
    for (int z = 0; z < NSPLIT; ++z) a += g_out_part[(size_t)z * Bb * Dd + i];
    out[i] = a;
}

// ---------------- launch -------------------------------------------------------------
extern "C" void kernel_launch(void* const* d_in, const int* in_sizes, int n_in,
                              void* d_out, int out_size) {
    const float* X       = (const float*)d_in[0];
    const int*   lengths = (const int*)d_in[1];
    const float* Wg      = (const float*)d_in[2];
    const float* Wl      = (const float*)d_in[3];
    float* out = (float*)d_out;

    cudaFuncSetAttribute(k_norm, cudaFuncAttributeMaxDynamicSharedMemorySize, NORM_SMEM);

    k_transpose<<<dim3(Dd / 32, Dd / 32), dim3(32, 32)>>>(Wl);
    k_prep<<<dim3(Dd / 256, Bb, NSPLIT), 256>>>(X, lengths);
    k_gp1<<<dim3(4, 8), 256>>>(Wg);
    k_gp2<<<Bb, 256>>>();
    k_v1<<<dim3(4, 16), 256>>>();
    k_v2<<<(Bb * Dd) / 256, 256>>>();
    k_norm<<<(Bb * Ss) / 128, 256, NORM_SMEM>>>(lengths);
    k_att<<<(Bb * Ss) / 8, 256>>>(X, lengths);
    k_out<<<dim3(Dd / 256, Bb, NSPLIT), 256>>>(X, lengths);
    k_final<<<(Bb * Dd) / 256, 256>>>(out);
}

// round 5
// speedup vs baseline: 1.2680x; 1.0508x over previous
#include <cuda_runtime.h>
#include <cuda_bf16.h>
#include <cstdint>

#define Bb 32
#define Ss 2048
#define Dd 1024
#define NSPLIT 8
#define SCHUNK (Ss / NSPLIT)

// ---------------- scratch (device globals; no allocation allowed) ----------------
__device__ alignas(16) __nv_bfloat16 g_Xbf[(size_t)Bb * Ss * Dd];   // masked bf16 X
__device__ alignas(16) __nv_bfloat16 g_Wt[(size_t)Dd * Dd];         // Wt[e][d] = Wl[d][e]
__device__ alignas(16) float g_Wlt[(size_t)Dd * Dd];                // fp32 transpose of Wl
__device__ alignas(16) float g_gsum_part[NSPLIT * Bb * Dd];
__device__ float g_gppart[8 * Bb * Dd];
__device__ float g_gp[Bb * Dd];       // RAW (unnormalized) gp
__device__ float g_rsq[Bb];
__device__ float g_vpart[16 * Bb * Dd];
__device__ alignas(16) float g_v[Bb * Dd];   // v = (Wl @ gp) * rsq (fp32 exact)
__device__ float g_nrm[Bb * Ss];             // ||x @ Wl||^2 per token
__device__ alignas(16) float g_out_part[NSPLIT * Bb * Dd];

// ---------------- helpers ----------------------------------------------------------
__device__ __forceinline__ uint32_t smem_u32(const void* p) {
    return (uint32_t)__cvta_generic_to_shared(p);
}
__device__ __forceinline__ void cpa16(uint32_t dst, const void* src) {
    asm volatile("cp.async.cg.shared.global [%0], [%1], 16;\n" :: "r"(dst), "l"(src));
}
__device__ __forceinline__ void ldsm4(uint32_t& r0, uint32_t& r1, uint32_t& r2, uint32_t& r3,
                                      uint32_t addr) {
    asm volatile("ldmatrix.sync.aligned.m8n8.x4.shared.b16 {%0,%1,%2,%3}, [%4];"
                 : "=r"(r0), "=r"(r1), "=r"(r2), "=r"(r3) : "r"(addr));
}
__device__ __forceinline__ void mma_bf16(float c[4], uint32_t a0, uint32_t a1, uint32_t a2,
                                         uint32_t a3, uint32_t b0, uint32_t b1) {
    asm volatile(
        "mma.sync.aligned.m16n8k16.row.col.f32.bf16.bf16.f32 "
        "{%0,%1,%2,%3},{%4,%5,%6,%7},{%8,%9},{%0,%1,%2,%3};\n"
        : "+f"(c[0]), "+f"(c[1]), "+f"(c[2]), "+f"(c[3])
        : "r"(a0), "r"(a1), "r"(a2), "r"(a3), "r"(b0), "r"(b1));
}

// ---------------- K0: transpose Wl -> bf16 g_Wt + fp32 g_Wlt ----------------------
__global__ void k_transpose(const float* __restrict__ Wl) {
    __shared__ float tile[32][33];
    int x = blockIdx.x * 32 + threadIdx.x;
    int y = blockIdx.y * 32 + threadIdx.y;
    tile[threadIdx.y][threadIdx.x] = Wl[(size_t)y * Dd + x];
    __syncthreads();
    int xo = blockIdx.y * 32 + threadIdx.x;   // d
    int yo = blockIdx.x * 32 + threadIdx.y;   // e
    float v = tile[threadIdx.x][threadIdx.y];
    g_Wt[(size_t)yo * Dd + xo]  = __float2bfloat16(v);
    g_Wlt[(size_t)yo * Dd + xo] = v;
}

// ---------------- K1: mask + seq-sum partials + bf16 convert (vectorized) ---------
__global__ void __launch_bounds__(256) k_prep(const float* __restrict__ X,
                                              const int* __restrict__ lengths) {
    int b = blockIdx.y, z = blockIdx.z;
    int t = threadIdx.x;                       // owns float4 lane t of 256
    int len = lengths[b], s0 = z * SCHUNK;
    const float4* Xb = reinterpret_cast<const float4*>(X + (size_t)b * Ss * Dd) + t;
    uint2* Xo = reinterpret_cast<uint2*>(g_Xbf + (size_t)b * Ss * Dd) + t;
    int zlim = (len + 127) & ~127; if (zlim > Ss) zlim = Ss;

    float4 acc = make_float4(0.f, 0.f, 0.f, 0.f);
    int send = min(len, s0 + SCHUNK);
    int s = s0;
    for (; s + 2 <= send; s += 2) {
        float4 x0 = Xb[(size_t)s * 256];
        float4 x1 = Xb[(size_t)(s + 1) * 256];
        acc.x += x0.x + x1.x; acc.y += x0.y + x1.y;
        acc.z += x0.z + x1.z; acc.w += x0.w + x1.w;
        __nv_bfloat162 l0 = __floats2bfloat162_rn(x0.x, x0.y);
        __nv_bfloat162 h0 = __floats2bfloat162_rn(x0.z, x0.w);
        __nv_bfloat162 l1 = __floats2bfloat162_rn(x1.x, x1.y);
        __nv_bfloat162 h1 = __floats2bfloat162_rn(x1.z, x1.w);
        uint2 p0, p1;
        p0.x = *reinterpret_cast<unsigned*>(&l0); p0.y = *reinterpret_cast<unsigned*>(&h0);
        p1.x = *reinterpret_cast<unsigned*>(&l1); p1.y = *reinterpret_cast<unsigned*>(&h1);
        Xo[(size_t)s * 256] = p0;
        Xo[(size_t)(s + 1) * 256] = p1;
    }
    for (; s < send; ++s) {
        float4 x0 = Xb[(size_t)s * 256];
        acc.x += x0.x; acc.y += x0.y; acc.z += x0.z; acc.w += x0.w;
        __nv_bfloat162 l0 = __floats2bfloat162_rn(x0.x, x0.y);
        __nv_bfloat162 h0 = __floats2bfloat162_rn(x0.z, x0.w);
        uint2 p0;
        p0.x = *reinterpret_cast<unsigned*>(&l0); p0.y = *reinterpret_cast<unsigned*>(&h0);
        Xo[(size_t)s * 256] = p0;
    }
    int zs = max(len, s0), ze = min(zlim, s0 + SCHUNK);
    for (int sz = zs; sz < ze; ++sz) Xo[(size_t)sz * 256] = make_uint2(0u, 0u);

    reinterpret_cast<float4*>(g_gsum_part)[((size_t)z * Bb + b) * 256 + t] = acc;
}

// ---------------- gp chain: read Wg once, b-batched --------------------------------
__global__ void k_gp1(const float* __restrict__ Wg) {
    __shared__ float sgs[32][128];
    int tid = threadIdx.x;
    int y = blockIdx.y;                 // d2-split of 8
    for (int idx = tid; idx < 32 * 128; idx += 256) {
        int b2 = idx >> 7, d = idx & 127;
        float s = 0.f;
        #pragma unroll
        for (int z = 0; z < NSPLIT; ++z)
            s += g_gsum_part[((size_t)z * Bb + b2) * Dd + y * 128 + d];
        sgs[b2][d] = s;
    }
    __syncthreads();
    int col = blockIdx.x * 256 + tid;
    float acc[32];
    #pragma unroll
    for (int b2 = 0; b2 < 32; ++b2) acc[b2] = 0.f;
    for (int d2 = 0; d2 < 128; ++d2) {
        float w = Wg[(size_t)(y * 128 + d2) * Dd + col];
        #pragma unroll
        for (int b2 = 0; b2 < 32; ++b2) acc[b2] = fmaf(sgs[b2][d2], w, acc[b2]);
    }
    #pragma unroll
    for (int b2 = 0; b2 < 32; ++b2)
        g_gppart[((size_t)y * Bb + b2) * Dd + col] = acc[b2];
}

__global__ void k_gp2() {
    int b = blockIdx.x, tid = threadIdx.x;
    int lane = tid & 31, warp = tid >> 5;
    __shared__ float red[8];
    float sq = 0.f;
    for (int c = tid; c < Dd; c += 256) {
        float s = 0.f;
        #pragma unroll
        for (int z = 0; z < 8; ++z) s += g_gppart[((size_t)z * Bb + b) * Dd + c];
        g_gp[b * Dd + c] = s;
        sq += s * s;
    }
    #pragma unroll
    for (int o = 16; o; o >>= 1) sq += __shfl_xor_sync(0xffffffffu, sq, o);
    if (lane == 0) red[warp] = sq;
    __syncthreads();
    if (tid == 0) {
        float t = 0.f;
        #pragma unroll
        for (int w = 0; w < 8; ++w) t += red[w];
        g_rsq[b] = rsqrtf(fmaxf(t, 1e-12f));
    }
}

// ---------------- v chain: v = (Wl @ gp) * rsq, read Wlt once ----------------------
__global__ void k_v1() {
    __shared__ float sgp[32][64];
    int tid = threadIdx.x;
    int y = blockIdx.y;                 // e-split of 16
    for (int idx = tid; idx < 32 * 64; idx += 256) {
        int b2 = idx >> 6, e = idx & 63;
        sgp[b2][e] = g_gp[b2 * Dd + y * 64 + e];
    }
    __syncthreads();
    int col = blockIdx.x * 256 + tid;
    float acc[32];
    #pragma unroll
    for (int b2 = 0; b2 < 32; ++b2) acc[b2] = 0.f;
    for (int e = 0; e < 64; ++e) {
        float w = g_Wlt[(size_t)(y * 64 + e) * Dd + col];
        #pragma unroll
        for (int b2 = 0; b2 < 32; ++b2) acc[b2] = fmaf(sgp[b2][e], w, acc[b2]);
    }
    #pragma unroll
    for (int b2 = 0; b2 < 32; ++b2)
        g_vpart[((size_t)y * Bb + b2) * Dd + col] = acc[b2];
}

__global__ void k_v2() {
    int i = blockIdx.x * 256 + threadIdx.x;
    int b = i >> 10;
    float s = 0.f;
    #pragma unroll
    for (int z = 0; z < 16; ++z) s += g_vpart[(size_t)z * Bb * Dd + i];
    g_v[i] = s * g_rsq[b];
}

// ---------------- K3: HMMA GEMM, epilogue = row sums of squares --------------------
#define PITCH 80
#define STG_BYTES (128 * PITCH)                   // 10240
#define SA_OFF(st) ((uint32_t)(st) * 2u * STG_BYTES)
#define SB_OFF(st) ((uint32_t)(st) * 2u * STG_BYTES + STG_BYTES)
#define REDN_OFF 81920
#define NORM_SMEM 84096

__device__ __forceinline__ void fill_stage(uint32_t sb, int st, const char* Abase,
                                           const char* Bbase, int ks, int tid) {
    #pragma unroll
    for (int rep = 0; rep < 2; ++rep) {
        int id = tid + rep * 256;
        int r = id >> 2, c = id & 3;
        uint32_t off = (uint32_t)(r * PITCH + c * 16);
        cpa16(sb + SA_OFF(st) + off, Abase + (size_t)r * 2048 + ks * 64 + c * 16);
        cpa16(sb + SB_OFF(st) + off, Bbase + (size_t)r * 2048 + ks * 64 + c * 16);
    }
}

__global__ void __launch_bounds__(256, 2) k_norm(const int* __restrict__ lengths) {
    extern __shared__ __align__(128) char sm[];
    const int rows_base = blockIdx.x * 128;
    const int b = rows_base >> 11;
    if ((rows_base & (Ss - 1)) >= lengths[b]) return;

    const uint32_t sb = smem_u32(sm);
    float* redN = (float*)(sm + REDN_OFF);   // [4][128]

    const int tid = threadIdx.x;
    const int warp = tid >> 5, lane = tid & 31;
    const int wm = warp & 1, wn = warp >> 1;
    const int gid = lane >> 2, tig = lane & 3;
    const uint32_t lanebyte = (uint32_t)((lane & 15) * PITCH + (lane >> 4) * 16);

    const char* Abase = (const char*)(g_Xbf + (size_t)rows_base * Dd);   // 2048 B/row

    float rsN[4][2];
    #pragma unroll
    for (int i = 0; i < 4; ++i) { rsN[i][0] = 0.f; rsN[i][1] = 0.f; }

    for (int nt = 0; nt < 8; ++nt) {
        const char* Bbase = (const char*)g_Wt + (size_t)nt * 128 * 2048;

        #pragma unroll
        for (int st = 0; st < 3; ++st) {
            fill_stage(sb, st, Abase, Bbase, st, tid);
            asm volatile("cp.async.commit_group;");
        }

        float acc[4][4][4];
        #pragma unroll
        for (int i = 0; i < 4; ++i)
            #pragma unroll
            for (int j = 0; j < 4; ++j)
                #pragma unroll
                for (int q = 0; q < 4; ++q) acc[i][j][q] = 0.f;

        for (int ks = 0; ks < 32; ++ks) {
            asm volatile("cp.async.wait_group 2;");
            __syncthreads();
            // fill free stage first (overlaps with MMA below); commit every iter
            if (ks + 3 < 32) fill_stage(sb, (ks + 3) & 3, Abase, Bbase, ks + 3, tid);
            asm volatile("cp.async.commit_group;");

            const uint32_t sa = sb + SA_OFF(ks & 3);
            const uint32_t sB = sb + SB_OFF(ks & 3);
            #pragma unroll
            for (int kg = 0; kg < 2; ++kg) {
                uint32_t a[4][4];
                #pragma unroll
                for (int i = 0; i < 4; ++i)
                    ldsm4(a[i][0], a[i][1], a[i][2], a[i][3],
                          sa + (uint32_t)((wm * 64 + i * 16) * PITCH + kg * 32) + lanebyte);
                uint32_t bb[2][4];
                #pragma unroll
                for (int j2 = 0; j2 < 2; ++j2)
                    ldsm4(bb[j2][0], bb[j2][1], bb[j2][2], bb[j2][3],
                          sB + (uint32_t)((wn * 32 + j2 * 16) * PITCH + kg * 32) + lanebyte);
                #pragma unroll
                for (int i = 0; i < 4; ++i)
                    #pragma unroll
                    for (int j = 0; j < 4; ++j)
                        mma_bf16(acc[i][j], a[i][0], a[i][1], a[i][2], a[i][3],
                                 bb[j >> 1][j & 1], bb[j >> 1][(j & 1) + 2]);
            }
        }

        // epilogue: n += y^2 (no cancellation -> bf16-safe)
        #pragma unroll
        for (int j = 0; j < 4; ++j)
            #pragma unroll
            for (int i = 0; i < 4; ++i) {
                rsN[i][0] += acc[i][j][0] * acc[i][j][0] + acc[i][j][1] * acc[i][j][1];
                rsN[i][1] += acc[i][j][2] * acc[i][j][2] + acc[i][j][3] * acc[i][j][3];
            }
        __syncthreads();   // all ldmatrix reads done before next nt's prologue fills
    }

    #pragma unroll
    for (int i = 0; i < 4; ++i) {
        #pragma unroll
        for (int h = 0; h < 2; ++h) {
            float n = rsN[i][h];
            n += __shfl_xor_sync(0xffffffffu, n, 1);
            n += __shfl_xor_sync(0xffffffffu, n, 2);
            if (tig == 0) redN[wn * 128 + wm * 64 + i * 16 + gid + h * 8] = n;
        }
    }
    __syncthreads();
    if (tid < 128) {
        float n = (redN[tid] + redN[128 + tid]) + (redN[256 + tid] + redN[384 + tid]);
        g_nrm[rows_base + tid] = n;
    }
}

// ---------------- K4: fused attention + pooling ------------------------------------
// block = (b, z-chunk of 256 tokens), 8 warps; warp processes 32 tokens.
// Per token: dot t = x.v from registers, att = t * rsqrt(n), out += att * x (same regs).
__global__ void __launch_bounds__(256) k_pool(const float* __restrict__ X,
                                              const int* __restrict__ lengths) {
    __shared__ float4 sOut[8][256];
    int b = blockIdx.y, z = blockIdx.x;
    int warp = threadIdx.x >> 5, lane = threadIdx.x & 31;
    int len = lengths[b];

    const float4* v4 = reinterpret_cast<const float4*>(g_v + (size_t)b * Dd);
    float4 vr[8];
    #pragma unroll
    for (int i = 0; i < 8; ++i) vr[i] = v4[lane + 32 * i];

    float4 oa[8];
    #pragma unroll
    for (int i = 0; i < 8; ++i) oa[i] = make_float4(0.f, 0.f, 0.f, 0.f);

    int sw0 = z * SCHUNK + warp * 32;
    int swend = min(len, sw0 + 32);
    for (int s = sw0; s < swend; ++s) {
        const float4* x4 = reinterpret_cast<const float4*>(X + ((size_t)b * Ss + s) * Dd);
        float4 xr[8];
        float t = 0.f;
        #pragma unroll
        for (int i = 0; i < 8; ++i) {
            xr[i] = x4[lane + 32 * i];
            t += xr[i].x * vr[i].x + xr[i].y * vr[i].y +
                 xr[i].z * vr[i].z + xr[i].w * vr[i].w;
        }
        #pragma unroll
        for (int o = 16; o; o >>= 1) t += __shfl_xor_sync(0xffffffffu, t, o);
        float att = t * rsqrtf(fmaxf(g_nrm[(size_t)b * Ss + s], 1e-12f));
        #pragma unroll
        for (int i = 0; i < 8; ++i) {
            oa[i].x = fmaf(att, xr[i].x, oa[i].x);
            oa[i].y = fmaf(att, xr[i].y, oa[i].y);
            oa[i].z = fmaf(att, xr[i].z, oa[i].z);
            oa[i].w = fmaf(att, xr[i].w, oa[i].w);
        }
    }
    #pragma unroll
    for (int i = 0; i < 8; ++i) sOut[warp][lane + 32 * i] = oa[i];
    __syncthreads();

    int f = threadIdx.x;             // float4 index 0..255
    float4 r = sOut[0][f];
    #pragma unroll
    for (int w = 1; w < 8; ++w) {
        float4 q = sOut[w][f];
        r.x += q.x; r.y += q.y; r.z += q.z; r.w += q.w;
    }
    reinterpret_cast<float4*>(g_out_part)[((size_t)z * Bb + b) * 256 + f] = r;
}

// ---------------- K6: combine partials ----------------------------------------------
__global__ void k_final(float* __restrict__ out) {
    int i = blockIdx.x * 256 + threadIdx.x;
    float a = 0.f;
    #pragma unroll
    for (int z = 0; z < NSPLIT; ++z) a += g_out_part[(size_t)z * Bb * Dd + i];
    out[i] = a;
}

// ---------------- launch -------------------------------------------------------------
extern "C" void kernel_launch(void* const* d_in, const int* in_sizes, int n_in,
                              void* d_out, int out_size) {
    const float* X       = (const float*)d_in[0];
    const int*   lengths = (const int*)d_in[1];
    const float* Wg      = (const float*)d_in[2];
    const float* Wl      = (const float*)d_in[3];
    float* out = (float*)d_out;

    cudaFuncSetAttribute(k_norm, cudaFuncAttributeMaxDynamicSharedMemorySize, NORM_SMEM);

    // k_norm placed at launch index 5 so ncu (-s 5 -c 1) profiles it next round.
    k_transpose<<<dim3(Dd / 32, Dd / 32), dim3(32, 32)>>>(Wl);       // 0
    k_prep<<<dim3(1, Bb, NSPLIT), 256>>>(X, lengths);                // 1
    k_gp1<<<dim3(4, 8), 256>>>(Wg);                                  // 2
    k_gp2<<<Bb, 256>>>();                                            // 3
    k_v1<<<dim3(4, 16), 256>>>();                                    // 4
    k_norm<<<(Bb * Ss) / 128, 256, NORM_SMEM>>>(lengths);            // 5  (profiled)
    k_v2<<<(Bb * Dd) / 256, 256>>>();                                // 6
    k_pool<<<dim3(NSPLIT, Bb), 256>>>(X, lengths);                   // 7
    k_final<<<(Bb * Dd) / 256, 256>>>(out);                          // 8
}